// round 5
// baseline (speedup 1.0000x reference)
#include <cuda_runtime.h>
#include <math.h>

// Problem constants (fixed by setup_inputs)
#define Bsz    2
#define Hh     256
#define Ww     256
#define Cc     192
#define C3     576
#define HEADS  4
#define CPH    48
#define HWn    65536
#define Mrows  131072   // B*H*W
#define Kdim   192

// ---------------- scratch (static device globals: allocation-free) ----------
__device__ float g_qkv1[(size_t)Mrows * C3];     // after 1x1 qkv conv   (302 MB)
__device__ float g_qkv2[(size_t)Mrows * C3];     // after depthwise conv (302 MB)
__device__ float g_attn[(size_t)Mrows * Cc];     // attention output     (100 MB)
__device__ float g_norms[Bsz * 384];             // sumsq for q(0..191), k(192..383)
__device__ float g_S[Bsz * HEADS * CPH * CPH];   // raw gram logits
__device__ float g_A[Bsz * HEADS * CPH * CPH];   // softmax, stored [bh][j][i]

// ---------------- K0: zero the accumulated buffers (every launch!) ----------
__global__ void zero_kernel(float* __restrict__ norms, float* __restrict__ S)
{
    int t = blockIdx.x * 256 + threadIdx.x;
    if (t < Bsz * 384) norms[t] = 0.f;
    if (t < Bsz * HEADS * CPH * CPH) S[t] = 0.f;
}

// ---------------- K1/K7: SGEMM C[M,N] = A[M,192] * W[192,N] + bias ---------
// BM=128, BN=96, BK=16, 256 threads (16x16), thread tile 8x6, double-buffered.
__global__ __launch_bounds__(256, 2)
void sgemm_bias_kernel(const float* __restrict__ A, const float* __restrict__ W,
                       const float* __restrict__ bias, float* __restrict__ C,
                       int N)
{
    __shared__ __align__(16) float As[2][16 * 128];   // [k][m]
    __shared__ __align__(16) float Ws[2][16 * 96];    // [k][n]

    const int tid  = threadIdx.x;
    const int tx   = tid & 15;       // 0..15 -> 6 cols
    const int ty   = tid >> 4;       // 0..15 -> 8 rows
    const int row0 = blockIdx.y * 128;
    const int n0   = blockIdx.x * 96;

    // A tile: 512 float4 (128 rows x 16 k), 2 per thread
    const int ar0  = tid >> 2;            // row within tile (0..63), second at +64
    const int akq0 = (tid & 3) * 4;       // k offset within tile (0,4,8,12)
    // W tile: 768 float2 (16 k x 96 n), 3 per thread
    int wk[3], wc[3];
#pragma unroll
    for (int p = 0; p < 3; ++p) {
        int idx = tid + 256 * p;
        wk[p] = idx / 48;
        wc[p] = idx - wk[p] * 48;
    }

    float4 a0, a1;
    float2 w0, w1, w2;

    auto LDG = [&](int t) {
        const int k0 = t * 16;
        a0 = *(const float4*)&A[(size_t)(row0 + ar0)      * Kdim + k0 + akq0];
        a1 = *(const float4*)&A[(size_t)(row0 + ar0 + 64) * Kdim + k0 + akq0];
        w0 = *(const float2*)&W[(size_t)(k0 + wk[0]) * N + n0 + wc[0] * 2];
        w1 = *(const float2*)&W[(size_t)(k0 + wk[1]) * N + n0 + wc[1] * 2];
        w2 = *(const float2*)&W[(size_t)(k0 + wk[2]) * N + n0 + wc[2] * 2];
    };
    auto STS = [&](int buf) {
        float* as = As[buf];
        float* ws = Ws[buf];
        as[(akq0 + 0) * 128 + ar0] = a0.x;
        as[(akq0 + 1) * 128 + ar0] = a0.y;
        as[(akq0 + 2) * 128 + ar0] = a0.z;
        as[(akq0 + 3) * 128 + ar0] = a0.w;
        as[(akq0 + 0) * 128 + ar0 + 64] = a1.x;
        as[(akq0 + 1) * 128 + ar0 + 64] = a1.y;
        as[(akq0 + 2) * 128 + ar0 + 64] = a1.z;
        as[(akq0 + 3) * 128 + ar0 + 64] = a1.w;
        ws[wk[0] * 96 + wc[0] * 2]     = w0.x;
        ws[wk[0] * 96 + wc[0] * 2 + 1] = w0.y;
        ws[wk[1] * 96 + wc[1] * 2]     = w1.x;
        ws[wk[1] * 96 + wc[1] * 2 + 1] = w1.y;
        ws[wk[2] * 96 + wc[2] * 2]     = w2.x;
        ws[wk[2] * 96 + wc[2] * 2 + 1] = w2.y;
    };

    float acc[8][6];
#pragma unroll
    for (int i = 0; i < 8; ++i)
#pragma unroll
        for (int j = 0; j < 6; ++j) acc[i][j] = 0.f;

    LDG(0);
    STS(0);
    __syncthreads();

#pragma unroll 1
    for (int t = 0; t < 12; ++t) {          // K = 192 = 12 * 16
        const int cur = t & 1;
        if (t < 11) LDG(t + 1);
        const float* as = As[cur];
        const float* ws = Ws[cur];
#pragma unroll
        for (int kk = 0; kk < 16; ++kk) {
            float4 fa0 = *(const float4*)&as[kk * 128 + ty * 8];
            float4 fa1 = *(const float4*)&as[kk * 128 + ty * 8 + 4];
            float2 fb0 = *(const float2*)&ws[kk * 96 + tx * 2];
            float2 fb1 = *(const float2*)&ws[kk * 96 + tx * 2 + 32];
            float2 fb2 = *(const float2*)&ws[kk * 96 + tx * 2 + 64];
            float ar[8] = {fa0.x, fa0.y, fa0.z, fa0.w, fa1.x, fa1.y, fa1.z, fa1.w};
            float br[6] = {fb0.x, fb0.y, fb1.x, fb1.y, fb2.x, fb2.y};
#pragma unroll
            for (int i = 0; i < 8; ++i)
#pragma unroll
                for (int j = 0; j < 6; ++j) acc[i][j] += ar[i] * br[j];
        }
        if (t < 11) {
            STS((t + 1) & 1);
            __syncthreads();
        }
    }

    float bia[6];
#pragma unroll
    for (int j = 0; j < 6; ++j)
        bia[j] = bias[n0 + (j >> 1) * 32 + tx * 2 + (j & 1)];

#pragma unroll
    for (int i = 0; i < 8; ++i) {
        size_t ro = (size_t)(row0 + ty * 8 + i) * N + n0;
#pragma unroll
        for (int g = 0; g < 3; ++g) {
            float2 st;
            st.x = acc[i][2 * g]     + bia[2 * g];
            st.y = acc[i][2 * g + 1] + bia[2 * g + 1];
            *(float2*)&C[ro + g * 32 + tx * 2] = st;
        }
    }
}

// ---------------- K2: 3x3 depthwise conv, SAME padding, 576 channels -------
// Thread = one float4 of channels at one pixel. NHWC means (pixel, channel)
// is fully contiguous; vertical taps hit L2 (3-row window = 1.7 MB << 126 MB).
__global__ void dwconv_kernel(const float* __restrict__ in,
                              const float* __restrict__ wdw,
                              const float* __restrict__ bias,
                              float* __restrict__ out)
{
    const int NC4 = C3 / 4;  // 144
    int gid = blockIdx.x * 256 + threadIdx.x;
    if (gid >= Bsz * HWn * NC4) return;
    int c4  = gid % NC4;
    int pix = gid / NC4;
    int x = pix & (Ww - 1);
    int y = (pix >> 8) & (Hh - 1);

    const float4* in4 = (const float4*)in;
    const float4* w4  = (const float4*)wdw;
    float4 acc = ((const float4*)bias)[c4];
#pragma unroll
    for (int dy = -1; dy <= 1; ++dy) {
        int yy = y + dy;
        if ((unsigned)yy >= (unsigned)Hh) continue;
#pragma unroll
        for (int dx = -1; dx <= 1; ++dx) {
            int xx = x + dx;
            if ((unsigned)xx >= (unsigned)Ww) continue;
            float4 v  = in4[(size_t)(pix + dy * Ww + dx) * NC4 + c4];
            float4 wv = w4[((dy + 1) * 3 + (dx + 1)) * NC4 + c4];
            acc.x += v.x * wv.x;
            acc.y += v.y * wv.y;
            acc.z += v.z * wv.z;
            acc.w += v.w * wv.w;
        }
    }
    ((float4*)out)[(size_t)pix * NC4 + c4] = acc;
}

// ---------------- K3: per-channel sum of squares over HW (q & k only) -------
// grid (64 hw-splits, 3 channel-chunks of 128, 2 batch); block 256 = 128ch x 2hw
__global__ void norms_kernel(const float* __restrict__ qkv, float* __restrict__ norms)
{
    int b  = blockIdx.z;
    int cg = blockIdx.y;
    int sp = blockIdx.x;
    int t  = threadIdx.x;
    int ch = t & 127;
    int hs = t >> 7;
    int chg = cg * 128 + ch;     // 0..383

    const float* base = qkv + (size_t)b * HWn * C3 + chg;
    float s = 0.f;
#pragma unroll 8
    for (int i = 0; i < 512; ++i) {
        int hw = sp * 1024 + i * 2 + hs;
        float v = base[(size_t)hw * C3];
        s += v * v;
    }
    __shared__ float red[256];
    red[t] = s;
    __syncthreads();
    if (hs == 0)
        atomicAdd(&norms[b * 384 + chg], red[t] + red[t + 128]);
}

// ---------------- K4: raw gram S[bh][i][j] = sum_hw q_i * k_j (split-K) ----
// grid (8 bh, 128 splits of 512 hw); block 64 threads (8x8), tile 6x6.
__global__ __launch_bounds__(64)
void gram_kernel(const float* __restrict__ qkv, float* __restrict__ S)
{
    int bh   = blockIdx.x;
    int sp   = blockIdx.y;
    int b    = bh >> 2;
    int head = bh & 3;
    int t    = threadIdx.x;
    int ti   = t & 7;
    int tj   = t >> 3;

    __shared__ float sqk[2 * 16 * 48];   // [which][hw16][48]
    float acc[6][6];
#pragma unroll
    for (int i = 0; i < 6; ++i)
#pragma unroll
        for (int j = 0; j < 6; ++j) acc[i][j] = 0.f;

    const int chQ = head * CPH;
    const int chK = 192 + head * CPH;
    size_t rowbase = (size_t)(b * HWn + sp * 512) * C3;

#pragma unroll 1
    for (int chunk = 0; chunk < 32; ++chunk) {
        size_t cb = rowbase + (size_t)chunk * 16 * C3;
#pragma unroll
        for (int p = 0; p < 24; ++p) {
            int idx = t + p * 64;               // < 1536
            int which = idx >= 768;
            int r = idx - which * 768;
            int hwl = r / 48;
            int c = r - hwl * 48;
            sqk[which * 768 + hwl * 48 + c] =
                qkv[cb + (size_t)hwl * C3 + (which ? chK : chQ) + c];
        }
        __syncthreads();
#pragma unroll 8
        for (int kk = 0; kk < 16; ++kk) {
            float qa[6], kb[6];
#pragma unroll
            for (int ii = 0; ii < 6; ++ii) qa[ii] = sqk[kk * 48 + ti * 6 + ii];
#pragma unroll
            for (int jj = 0; jj < 6; ++jj) kb[jj] = sqk[768 + kk * 48 + tj * 6 + jj];
#pragma unroll
            for (int ii = 0; ii < 6; ++ii)
#pragma unroll
                for (int jj = 0; jj < 6; ++jj) acc[ii][jj] += qa[ii] * kb[jj];
        }
        __syncthreads();
    }

    float* Sb = S + (size_t)bh * CPH * CPH;
#pragma unroll
    for (int ii = 0; ii < 6; ++ii)
#pragma unroll
        for (int jj = 0; jj < 6; ++jj)
            atomicAdd(&Sb[(ti * 6 + ii) * CPH + tj * 6 + jj], acc[ii][jj]);
}

// ---------------- K5: normalize logits, temperature, softmax ----------------
// out stored transposed: A[bh][j][i]
__global__ void softmax_kernel(const float* __restrict__ S, const float* __restrict__ norms,
                               const float* __restrict__ temp, float* __restrict__ A)
{
    int bh = blockIdx.x;
    int b = bh >> 2, head = bh & 3;
    int t = threadIdx.x;   // 64, rows 0..47 active

    __shared__ float kn[CPH];
    if (t < CPH)
        kn[t] = fmaxf(sqrtf(norms[b * 384 + 192 + head * CPH + t]), 1e-12f);
    __syncthreads();

    if (t < CPH) {
        float qn = fmaxf(sqrtf(norms[b * 384 + head * CPH + t]), 1e-12f);
        float tp = temp[head];
        const float* Sr = S + ((size_t)bh * CPH + t) * CPH;
        float l[CPH];
        float m = -1e30f;
#pragma unroll
        for (int j = 0; j < CPH; ++j) {
            l[j] = Sr[j] * tp / (qn * kn[j]);
            m = fmaxf(m, l[j]);
        }
        float s = 0.f;
#pragma unroll
        for (int j = 0; j < CPH; ++j) {
            float e = expf(l[j] - m);
            l[j] = e;
            s += e;
        }
        float inv = 1.f / s;
        float* Ab = A + (size_t)bh * CPH * CPH;
#pragma unroll
        for (int j = 0; j < CPH; ++j)
            Ab[j * CPH + t] = l[j] * inv;   // transposed store
    }
}

// ---------------- K6: out[hw, head*48+i] = sum_j A[i][j] * v[j][hw] --------
// grid (512 hw-tiles of 128, 4 heads, 2 batch); block 64 threads, 2 hw each.
// Output staged through smem for coalesced stores.
__global__ __launch_bounds__(64)
void apply_kernel(const float* __restrict__ qkv, const float* __restrict__ A,
                  float* __restrict__ out)
{
    int hw0  = blockIdx.x * 128;
    int head = blockIdx.y;
    int b    = blockIdx.z;
    int t    = threadIdx.x;

    __shared__ __align__(16) float As2[CPH * CPH];   // [j][i]
    __shared__ float Vs[128 * 49];

    const float* Ab = A + (size_t)(b * HEADS + head) * CPH * CPH;
#pragma unroll
    for (int p = 0; p < 36; ++p) As2[t + p * 64] = Ab[t + p * 64];

    size_t base = (size_t)(b * HWn + hw0) * C3 + 384 + head * CPH;
#pragma unroll 4
    for (int p = 0; p < 96; ++p) {
        int idx = t + p * 64;              // < 6144
        int hwl = idx / 48;
        int c   = idx - hwl * 48;
        Vs[hwl * 49 + c] = qkv[base + (size_t)hwl * C3 + c];
    }
    __syncthreads();

    float acc0[CPH], acc1[CPH];
#pragma unroll
    for (int i = 0; i < CPH; ++i) { acc0[i] = 0.f; acc1[i] = 0.f; }

#pragma unroll 2
    for (int j = 0; j < CPH; ++j) {
        float v0 = Vs[t * 49 + j];
        float v1 = Vs[(t + 64) * 49 + j];
#pragma unroll
        for (int i4 = 0; i4 < 12; ++i4) {
            float4 a4 = *(const float4*)&As2[j * CPH + i4 * 4];
            acc0[i4 * 4 + 0] += a4.x * v0;  acc1[i4 * 4 + 0] += a4.x * v1;
            acc0[i4 * 4 + 1] += a4.y * v0;  acc1[i4 * 4 + 1] += a4.y * v1;
            acc0[i4 * 4 + 2] += a4.z * v0;  acc1[i4 * 4 + 2] += a4.z * v1;
            acc0[i4 * 4 + 3] += a4.w * v0;  acc1[i4 * 4 + 3] += a4.w * v1;
        }
    }

    __syncthreads();                       // done reading Vs; reuse as store stage
#pragma unroll
    for (int i = 0; i < CPH; ++i) {
        Vs[t * 49 + i]        = acc0[i];
        Vs[(t + 64) * 49 + i] = acc1[i];
    }
    __syncthreads();

    size_t obase = (size_t)(b * HWn + hw0) * Cc + head * CPH;
#pragma unroll 4
    for (int p = 0; p < 96; ++p) {
        int idx = t + p * 64;
        int hwl = idx / 48;
        int c   = idx - hwl * 48;
        out[obase + (size_t)hwl * Cc + c] = Vs[hwl * 49 + c];
    }
}

// ---------------- host launcher --------------------------------------------
extern "C" void kernel_launch(void* const* d_in, const int* in_sizes, int n_in,
                              void* d_out, int out_size)
{
    const float* x           = (const float*)d_in[0];
    const float* w_qkv       = (const float*)d_in[1];
    const float* b_qkv       = (const float*)d_in[2];
    const float* w_dw        = (const float*)d_in[3];
    const float* b_dw        = (const float*)d_in[4];
    const float* temperature = (const float*)d_in[5];
    const float* w_out       = (const float*)d_in[6];
    const float* b_out       = (const float*)d_in[7];
    float* out = (float*)d_out;

    float *qkv1, *qkv2, *attn, *norms, *S, *A;
    cudaGetSymbolAddress((void**)&qkv1,  g_qkv1);
    cudaGetSymbolAddress((void**)&qkv2,  g_qkv2);
    cudaGetSymbolAddress((void**)&attn,  g_attn);
    cudaGetSymbolAddress((void**)&norms, g_norms);
    cudaGetSymbolAddress((void**)&S,     g_S);
    cudaGetSymbolAddress((void**)&A,     g_A);

    // K0: zero accumulators (must happen on every graph replay)
    zero_kernel<<<72, 256>>>(norms, S);
    // K1: qkv 1x1 conv  [131072,192] x [192,576]
    sgemm_bias_kernel<<<dim3(C3 / 96, Mrows / 128), 256>>>(x, w_qkv, b_qkv, qkv1, C3);
    // K2: 3x3 depthwise conv
    dwconv_kernel<<<(Bsz * HWn * (C3 / 4)) / 256, 256>>>(qkv1, w_dw, b_dw, qkv2);
    // K3: L2-norm sums for q and k
    norms_kernel<<<dim3(64, 3, Bsz), 256>>>(qkv2, norms);
    // K4: gram logits
    gram_kernel<<<dim3(Bsz * HEADS, 128), 64>>>(qkv2, S);
    // K5: normalize + temperature + softmax
    softmax_kernel<<<Bsz * HEADS, 64>>>(S, norms, temperature, A);
    // K6: attn @ v
    apply_kernel<<<dim3(HWn / 128, HEADS, Bsz), 64>>>(qkv2, A, attn);
    // K7: output 1x1 conv [131072,192] x [192,192]
    sgemm_bias_kernel<<<dim3(Cc / 96, Mrows / 128), 256>>>(attn, w_out, b_out, out, Cc);
}

// round 11
// speedup vs baseline: 1.5746x; 1.5746x over previous
#include <cuda_runtime.h>
#include <cstdint>
#include <math.h>

// Problem constants (fixed by setup_inputs)
#define Bsz    2
#define Hh     256
#define Ww     256
#define Cc     192
#define C3     576
#define HEADS  4
#define CPH    48
#define HWn    65536
#define Mrows  131072   // B*H*W
#define Kdim   192

// ---------------- scratch (static device globals: allocation-free) ----------
__device__ float g_qkv1[(size_t)Mrows * C3];     // after 1x1 qkv conv
__device__ float g_qkv2[(size_t)Mrows * C3];     // after depthwise conv
__device__ float g_attn[(size_t)Mrows * Cc];     // attention output
__device__ float g_norms[Bsz * 384];             // sumsq q(0..191), k(192..383)
__device__ float g_S[Bsz * HEADS * CPH * CPH];   // raw gram logits
__device__ float g_A[Bsz * HEADS * CPH * CPH];   // softmax, stored [bh][j][i]
__device__ float g_wt1[C3 * Kdim];               // w_qkv^T  [576][192]
__device__ float g_wt2[Cc * Kdim];               // w_out^T  [192][192]

// ---------------- K0: zero the accumulated buffers (every replay) -----------
__global__ void zero_kernel(float* __restrict__ norms, float* __restrict__ S)
{
    int t = blockIdx.x * 256 + threadIdx.x;
    if (t < Bsz * 384) norms[t] = 0.f;
    if (t < Bsz * HEADS * CPH * CPH) S[t] = 0.f;
}

// ---------------- K-1: transpose W [192,N] -> Wt [N,192] --------------------
__global__ void transpose_w_kernel(const float* __restrict__ w,
                                   float* __restrict__ wt, int N)
{
    int idx = blockIdx.x * 256 + threadIdx.x;
    if (idx >= Kdim * N) return;
    int n = idx / Kdim;
    int k = idx - n * Kdim;
    wt[idx] = w[k * N + n];
}

// ===================== tf32 mma.sync GEMM: C = A * Wt^T + bias ==============
// BM=128, BN=96, BK=32, 256 threads = 8 warps (4 over M x 2 over N).
// Warp tile 32x48 = 2 m16 x 6 n8 mma tiles. SMEM rows padded to 36 floats
// -> fragment-load bank index (4*grp+tig)%32 is conflict-free.

__device__ __forceinline__ float to_tf32(float x) {
    float r;
    asm("cvt.rna.tf32.f32 %0, %1;" : "=f"(r) : "f"(x));
    return r;
}

__device__ __forceinline__ void mma_tf32(float4& d,
                                         uint32_t a0, uint32_t a1,
                                         uint32_t a2, uint32_t a3,
                                         uint32_t b0, uint32_t b1)
{
    asm volatile(
        "mma.sync.aligned.m16n8k8.row.col.f32.tf32.tf32.f32 "
        "{%0,%1,%2,%3}, {%4,%5,%6,%7}, {%8,%9}, {%0,%1,%2,%3};"
        : "+f"(d.x), "+f"(d.y), "+f"(d.z), "+f"(d.w)
        : "r"(a0), "r"(a1), "r"(a2), "r"(a3), "r"(b0), "r"(b1));
}

#define LDA_PAD   36                       // 128 rows x 36 floats
#define A_FLOATS  (128 * LDA_PAD)          // 4608
#define B_FLOATS  (96 * LDA_PAD)           // 3456
#define BUF_FLOATS (A_FLOATS + B_FLOATS)   // 8064
#define GEMM_SMEM (2 * BUF_FLOATS * 4)     // 64512 bytes

__global__ __launch_bounds__(256, 2)
void tc_gemm_kernel(const float* __restrict__ A, const float* __restrict__ Wt,
                    const float* __restrict__ bias, float* __restrict__ C, int N)
{
    extern __shared__ __align__(16) float smem[];

    const int tid  = threadIdx.x;
    const int wid  = tid >> 5;
    const int lane = tid & 31;
    const int grp  = lane >> 2;        // 0..7
    const int tig  = lane & 3;         // 0..3
    const int wm   = wid & 3;          // warp row (M)
    const int wn   = wid >> 2;         // warp col (N)
    const int n0   = blockIdx.x * 96;
    const int row0 = blockIdx.y * 128;

    // global-load staging registers
    float4 gA[4], gB[3];

    auto LDG = [&](int t) {
        const int k0 = t * 32;
#pragma unroll
        for (int i = 0; i < 4; ++i) {
            int f = tid + i * 256;             // < 1024 float4 (128 rows x 8)
            int r = f >> 3;
            int c = (f & 7) * 4;
            gA[i] = *(const float4*)&A[(size_t)(row0 + r) * Kdim + k0 + c];
        }
#pragma unroll
        for (int i = 0; i < 3; ++i) {
            int f = tid + i * 256;             // < 768 float4 (96 rows x 8)
            int r = f >> 3;
            int c = (f & 7) * 4;
            gB[i] = *(const float4*)&Wt[(size_t)(n0 + r) * Kdim + k0 + c];
        }
    };
    auto STS = [&](int buf) {
        float* As = smem + buf * BUF_FLOATS;
        float* Bs = As + A_FLOATS;
#pragma unroll
        for (int i = 0; i < 4; ++i) {
            int f = tid + i * 256;
            int r = f >> 3;
            int c = (f & 7) * 4;
            float4 v = gA[i];
            v.x = to_tf32(v.x); v.y = to_tf32(v.y);
            v.z = to_tf32(v.z); v.w = to_tf32(v.w);
            *(float4*)&As[r * LDA_PAD + c] = v;       // 144B row stride: aligned
        }
#pragma unroll
        for (int i = 0; i < 3; ++i) {
            int f = tid + i * 256;
            int r = f >> 3;
            int c = (f & 7) * 4;
            float4 v = gB[i];
            v.x = to_tf32(v.x); v.y = to_tf32(v.y);
            v.z = to_tf32(v.z); v.w = to_tf32(v.w);
            *(float4*)&Bs[r * LDA_PAD + c] = v;
        }
    };

    float4 acc[2][6];
#pragma unroll
    for (int mt = 0; mt < 2; ++mt)
#pragma unroll
        for (int nt = 0; nt < 6; ++nt)
            acc[mt][nt] = make_float4(0.f, 0.f, 0.f, 0.f);

    LDG(0);
    STS(0);
    __syncthreads();

#pragma unroll 1
    for (int t = 0; t < 6; ++t) {              // K = 192 = 6 * 32
        if (t < 5) LDG(t + 1);
        const float* As = smem + (t & 1) * BUF_FLOATS;
        const float* Bs = As + A_FLOATS;
#pragma unroll
        for (int ks = 0; ks < 4; ++ks) {
            const int kk = ks * 8;
            uint32_t af[2][4];
#pragma unroll
            for (int mt = 0; mt < 2; ++mt) {
                const float* ap = As + (wm * 32 + mt * 16 + grp) * LDA_PAD + kk + tig;
                af[mt][0] = __float_as_uint(ap[0]);
                af[mt][1] = __float_as_uint(ap[8 * LDA_PAD]);
                af[mt][2] = __float_as_uint(ap[4]);
                af[mt][3] = __float_as_uint(ap[8 * LDA_PAD + 4]);
            }
#pragma unroll
            for (int nt = 0; nt < 6; ++nt) {
                const float* bp = Bs + (wn * 48 + nt * 8 + grp) * LDA_PAD + kk + tig;
                uint32_t b0 = __float_as_uint(bp[0]);
                uint32_t b1 = __float_as_uint(bp[4]);
                mma_tf32(acc[0][nt], af[0][0], af[0][1], af[0][2], af[0][3], b0, b1);
                mma_tf32(acc[1][nt], af[1][0], af[1][1], af[1][2], af[1][3], b0, b1);
            }
        }
        if (t < 5) {
            STS((t + 1) & 1);
            __syncthreads();
        }
    }

    // epilogue: bias + store (float2, 32B-contiguous per 4-lane group)
#pragma unroll
    for (int mt = 0; mt < 2; ++mt) {
        int row = row0 + wm * 32 + mt * 16 + grp;
#pragma unroll
        for (int nt = 0; nt < 6; ++nt) {
            int col = n0 + wn * 48 + nt * 8 + tig * 2;
            float2 bv = *(const float2*)&bias[col];
            float4 a = acc[mt][nt];
            float2 v0 = {a.x + bv.x, a.y + bv.y};
            float2 v1 = {a.z + bv.x, a.w + bv.y};
            *(float2*)&C[(size_t)row * N + col]       = v0;
            *(float2*)&C[(size_t)(row + 8) * N + col] = v1;
        }
    }
}

// ---------------- K2: 3x3 depthwise conv, SAME padding, 576 channels -------
__global__ void dwconv_kernel(const float* __restrict__ in,
                              const float* __restrict__ wdw,
                              const float* __restrict__ bias,
                              float* __restrict__ out)
{
    const int NC4 = C3 / 4;  // 144
    int gid = blockIdx.x * 256 + threadIdx.x;
    if (gid >= Bsz * HWn * NC4) return;
    int c4  = gid % NC4;
    int pix = gid / NC4;
    int x = pix & (Ww - 1);
    int y = (pix >> 8) & (Hh - 1);

    const float4* in4 = (const float4*)in;
    const float4* w4  = (const float4*)wdw;
    float4 acc = ((const float4*)bias)[c4];
#pragma unroll
    for (int dy = -1; dy <= 1; ++dy) {
        int yy = y + dy;
        if ((unsigned)yy >= (unsigned)Hh) continue;
#pragma unroll
        for (int dx = -1; dx <= 1; ++dx) {
            int xx = x + dx;
            if ((unsigned)xx >= (unsigned)Ww) continue;
            float4 v  = in4[(size_t)(pix + dy * Ww + dx) * NC4 + c4];
            float4 wv = w4[((dy + 1) * 3 + (dx + 1)) * NC4 + c4];
            acc.x += v.x * wv.x;
            acc.y += v.y * wv.y;
            acc.z += v.z * wv.z;
            acc.w += v.w * wv.w;
        }
    }
    ((float4*)out)[(size_t)pix * NC4 + c4] = acc;
}

// ---------------- K3: per-channel sum of squares over HW (q & k only) -------
__global__ void norms_kernel(const float* __restrict__ qkv, float* __restrict__ norms)
{
    int b  = blockIdx.z;
    int cg = blockIdx.y;
    int sp = blockIdx.x;
    int t  = threadIdx.x;
    int ch = t & 127;
    int hs = t >> 7;
    int chg = cg * 128 + ch;     // 0..383

    const float* base = qkv + (size_t)b * HWn * C3 + chg;
    float s = 0.f;
#pragma unroll 8
    for (int i = 0; i < 512; ++i) {
        int hw = sp * 1024 + i * 2 + hs;
        float v = base[(size_t)hw * C3];
        s += v * v;
    }
    __shared__ float red[256];
    red[t] = s;
    __syncthreads();
    if (hs == 0)
        atomicAdd(&norms[b * 384 + chg], red[t] + red[t + 128]);
}

// ---------------- K4: raw gram S[bh][i][j] = sum_hw q_i * k_j (split-K) ----
__global__ __launch_bounds__(64)
void gram_kernel(const float* __restrict__ qkv, float* __restrict__ S)
{
    int bh   = blockIdx.x;
    int sp   = blockIdx.y;
    int b    = bh >> 2;
    int head = bh & 3;
    int t    = threadIdx.x;
    int ti   = t & 7;
    int tj   = t >> 3;

    __shared__ float sqk[2 * 16 * 48];
    float acc[6][6];
#pragma unroll
    for (int i = 0; i < 6; ++i)
#pragma unroll
        for (int j = 0; j < 6; ++j) acc[i][j] = 0.f;

    const int chQ = head * CPH;
    const int chK = 192 + head * CPH;
    size_t rowbase = (size_t)(b * HWn + sp * 512) * C3;

#pragma unroll 1
    for (int chunk = 0; chunk < 32; ++chunk) {
        size_t cb = rowbase + (size_t)chunk * 16 * C3;
#pragma unroll
        for (int p = 0; p < 24; ++p) {
            int idx = t + p * 64;
            int which = idx >= 768;
            int r = idx - which * 768;
            int hwl = r / 48;
            int c = r - hwl * 48;
            sqk[which * 768 + hwl * 48 + c] =
                qkv[cb + (size_t)hwl * C3 + (which ? chK : chQ) + c];
        }
        __syncthreads();
#pragma unroll 8
        for (int kk = 0; kk < 16; ++kk) {
            float qa[6], kb[6];
#pragma unroll
            for (int ii = 0; ii < 6; ++ii) qa[ii] = sqk[kk * 48 + ti * 6 + ii];
#pragma unroll
            for (int jj = 0; jj < 6; ++jj) kb[jj] = sqk[768 + kk * 48 + tj * 6 + jj];
#pragma unroll
            for (int ii = 0; ii < 6; ++ii)
#pragma unroll
                for (int jj = 0; jj < 6; ++jj) acc[ii][jj] += qa[ii] * kb[jj];
        }
        __syncthreads();
    }

    float* Sb = S + (size_t)bh * CPH * CPH;
#pragma unroll
    for (int ii = 0; ii < 6; ++ii)
#pragma unroll
        for (int jj = 0; jj < 6; ++jj)
            atomicAdd(&Sb[(ti * 6 + ii) * CPH + tj * 6 + jj], acc[ii][jj]);
}

// ---------------- K5: normalize logits, temperature, softmax ----------------
__global__ void softmax_kernel(const float* __restrict__ S, const float* __restrict__ norms,
                               const float* __restrict__ temp, float* __restrict__ A)
{
    int bh = blockIdx.x;
    int b = bh >> 2, head = bh & 3;
    int t = threadIdx.x;

    __shared__ float kn[CPH];
    if (t < CPH)
        kn[t] = fmaxf(sqrtf(norms[b * 384 + 192 + head * CPH + t]), 1e-12f);
    __syncthreads();

    if (t < CPH) {
        float qn = fmaxf(sqrtf(norms[b * 384 + head * CPH + t]), 1e-12f);
        float tp = temp[head];
        const float* Sr = S + ((size_t)bh * CPH + t) * CPH;
        float l[CPH];
        float m = -1e30f;
#pragma unroll
        for (int j = 0; j < CPH; ++j) {
            l[j] = Sr[j] * tp / (qn * kn[j]);
            m = fmaxf(m, l[j]);
        }
        float s = 0.f;
#pragma unroll
        for (int j = 0; j < CPH; ++j) {
            float e = expf(l[j] - m);
            l[j] = e;
            s += e;
        }
        float inv = 1.f / s;
        float* Ab = A + (size_t)bh * CPH * CPH;
#pragma unroll
        for (int j = 0; j < CPH; ++j)
            Ab[j * CPH + t] = l[j] * inv;   // transposed store
    }
}

// ---------------- K6: out[hw, head*48+i] = sum_j A[i][j] * v[j][hw] --------
__global__ __launch_bounds__(64)
void apply_kernel(const float* __restrict__ qkv, const float* __restrict__ A,
                  float* __restrict__ out)
{
    int hw0  = blockIdx.x * 128;
    int head = blockIdx.y;
    int b    = blockIdx.z;
    int t    = threadIdx.x;

    __shared__ __align__(16) float As2[CPH * CPH];
    __shared__ float Vs[128 * 49];

    const float* Ab = A + (size_t)(b * HEADS + head) * CPH * CPH;
#pragma unroll
    for (int p = 0; p < 36; ++p) As2[t + p * 64] = Ab[t + p * 64];

    size_t base = (size_t)(b * HWn + hw0) * C3 + 384 + head * CPH;
#pragma unroll 4
    for (int p = 0; p < 96; ++p) {
        int idx = t + p * 64;
        int hwl = idx / 48;
        int c   = idx - hwl * 48;
        Vs[hwl * 49 + c] = qkv[base + (size_t)hwl * C3 + c];
    }
    __syncthreads();

    float acc0[CPH], acc1[CPH];
#pragma unroll
    for (int i = 0; i < CPH; ++i) { acc0[i] = 0.f; acc1[i] = 0.f; }

#pragma unroll 2
    for (int j = 0; j < CPH; ++j) {
        float v0 = Vs[t * 49 + j];
        float v1 = Vs[(t + 64) * 49 + j];
#pragma unroll
        for (int i4 = 0; i4 < 12; ++i4) {
            float4 a4 = *(const float4*)&As2[j * CPH + i4 * 4];
            acc0[i4 * 4 + 0] += a4.x * v0;  acc1[i4 * 4 + 0] += a4.x * v1;
            acc0[i4 * 4 + 1] += a4.y * v0;  acc1[i4 * 4 + 1] += a4.y * v1;
            acc0[i4 * 4 + 2] += a4.z * v0;  acc1[i4 * 4 + 2] += a4.z * v1;
            acc0[i4 * 4 + 3] += a4.w * v0;  acc1[i4 * 4 + 3] += a4.w * v1;
        }
    }

    __syncthreads();
#pragma unroll
    for (int i = 0; i < CPH; ++i) {
        Vs[t * 49 + i]        = acc0[i];
        Vs[(t + 64) * 49 + i] = acc1[i];
    }
    __syncthreads();

    size_t obase = (size_t)(b * HWn + hw0) * Cc + head * CPH;
#pragma unroll 4
    for (int p = 0; p < 96; ++p) {
        int idx = t + p * 64;
        int hwl = idx / 48;
        int c   = idx - hwl * 48;
        out[obase + (size_t)hwl * Cc + c] = Vs[hwl * 49 + c];
    }
}

// ---------------- host launcher --------------------------------------------
extern "C" void kernel_launch(void* const* d_in, const int* in_sizes, int n_in,
                              void* d_out, int out_size)
{
    const float* x           = (const float*)d_in[0];
    const float* w_qkv       = (const float*)d_in[1];
    const float* b_qkv       = (const float*)d_in[2];
    const float* w_dw        = (const float*)d_in[3];
    const float* b_dw        = (const float*)d_in[4];
    const float* temperature = (const float*)d_in[5];
    const float* w_out       = (const float*)d_in[6];
    const float* b_out       = (const float*)d_in[7];
    float* out = (float*)d_out;

    float *qkv1, *qkv2, *attn, *norms, *S, *A, *wt1, *wt2;
    cudaGetSymbolAddress((void**)&qkv1,  g_qkv1);
    cudaGetSymbolAddress((void**)&qkv2,  g_qkv2);
    cudaGetSymbolAddress((void**)&attn,  g_attn);
    cudaGetSymbolAddress((void**)&norms, g_norms);
    cudaGetSymbolAddress((void**)&S,     g_S);
    cudaGetSymbolAddress((void**)&A,     g_A);
    cudaGetSymbolAddress((void**)&wt1,   g_wt1);
    cudaGetSymbolAddress((void**)&wt2,   g_wt2);

    cudaFuncSetAttribute(tc_gemm_kernel,
                         cudaFuncAttributeMaxDynamicSharedMemorySize, GEMM_SMEM);

    // K0: zero accumulators (every graph replay)
    zero_kernel<<<72, 256>>>(norms, S);
    // transpose weights into K-major scratch
    transpose_w_kernel<<<(Kdim * C3 + 255) / 256, 256>>>(w_qkv, wt1, C3);
    transpose_w_kernel<<<(Kdim * Cc + 255) / 256, 256>>>(w_out, wt2, Cc);
    // K1: qkv 1x1 conv  [131072,192] x [192,576]  (tf32 mma.sync)
    tc_gemm_kernel<<<dim3(C3 / 96, Mrows / 128), 256, GEMM_SMEM>>>(x, wt1, b_qkv, qkv1, C3);
    // K2: 3x3 depthwise conv
    dwconv_kernel<<<(Bsz * HWn * (C3 / 4)) / 256, 256>>>(qkv1, w_dw, b_dw, qkv2);
    // K3: L2-norm sums for q and k
    norms_kernel<<<dim3(64, 3, Bsz), 256>>>(qkv2, norms);
    // K4: gram logits
    gram_kernel<<<dim3(Bsz * HEADS, 128), 64>>>(qkv2, S);
    // K5: normalize + temperature + softmax
    softmax_kernel<<<Bsz * HEADS, 64>>>(S, norms, temperature, A);
    // K6: attn @ v
    apply_kernel<<<dim3(HWn / 128, HEADS, Bsz), 64>>>(qkv2, A, attn);
    // K7: output 1x1 conv [131072,192] x [192,192]  (tf32 mma.sync)
    tc_gemm_kernel<<<dim3(Cc / 96, Mrows / 128), 256, GEMM_SMEM>>>(attn, wt2, b_out, out, Cc);
}

// round 13
// speedup vs baseline: 1.6111x; 1.0232x over previous
#include <cuda_runtime.h>
#include <cstdint>
#include <math.h>

// Problem constants (fixed by setup_inputs)
#define Bsz    2
#define Hh     256
#define Ww     256
#define Cc     192
#define C3     576
#define HEADS  4
#define CPH    48
#define HWn    65536
#define Mrows  131072   // B*H*W
#define Kdim   192

// ---------------- scratch (static device globals: allocation-free) ----------
__device__ float g_qkv1[(size_t)Mrows * C3];     // after 1x1 qkv conv
__device__ float g_qkv2[(size_t)Mrows * C3];     // after depthwise conv
__device__ float g_attn[(size_t)Mrows * Cc];     // attention output
__device__ float g_norms[Bsz * 384];             // sumsq q(0..191), k(192..383)
__device__ float g_S[Bsz * HEADS * CPH * CPH];   // raw gram logits
__device__ float g_A[Bsz * HEADS * CPH * CPH];   // softmax, stored [bh][j][i]
__device__ float g_wt1[C3 * Kdim];               // w_qkv^T  [576][192]
__device__ float g_wt2[Cc * Kdim];               // w_out^T  [192][192]

// ---------------- K0: zero the accumulated buffers (every replay) -----------
__global__ void zero_kernel(float* __restrict__ norms, float* __restrict__ S)
{
    int t = blockIdx.x * 256 + threadIdx.x;
    if (t < Bsz * 384) norms[t] = 0.f;
    if (t < Bsz * HEADS * CPH * CPH) S[t] = 0.f;
}

// ---------------- K-1: transpose W [192,N] -> Wt [N,192] --------------------
__global__ void transpose_w_kernel(const float* __restrict__ w,
                                   float* __restrict__ wt, int N)
{
    int idx = blockIdx.x * 256 + threadIdx.x;
    if (idx >= Kdim * N) return;
    int n = idx / Kdim;
    int k = idx - n * Kdim;
    wt[idx] = w[k * N + n];
}

// ===================== tf32 mma.sync GEMM: C = A * Wt^T + bias ==============
// BM=256, BN=96, BK=32, 256 threads = 8 warps (4 over M x 2 over N).
// Warp tile 64x48 = 4 m16 x 6 n8 mma tiles -> 13.7 FLOP per LDS byte
// (was 10 at 32x48). SMEM rows padded to 36 floats: fragment-load bank index
// (4*grp+tig+kk)%32 conflict-free; STS.128 quarter-warp phases conflict-free.

__device__ __forceinline__ float to_tf32(float x) {
    float r;
    asm("cvt.rna.tf32.f32 %0, %1;" : "=f"(r) : "f"(x));
    return r;
}

__device__ __forceinline__ void mma_tf32(float4& d,
                                         uint32_t a0, uint32_t a1,
                                         uint32_t a2, uint32_t a3,
                                         uint32_t b0, uint32_t b1)
{
    asm volatile(
        "mma.sync.aligned.m16n8k8.row.col.f32.tf32.tf32.f32 "
        "{%0,%1,%2,%3}, {%4,%5,%6,%7}, {%8,%9}, {%0,%1,%2,%3};"
        : "+f"(d.x), "+f"(d.y), "+f"(d.z), "+f"(d.w)
        : "r"(a0), "r"(a1), "r"(a2), "r"(a3), "r"(b0), "r"(b1));
}

#define LDA_PAD   36
#define A_FLOATS  (256 * LDA_PAD)          // 9216
#define B_FLOATS  (96 * LDA_PAD)           // 3456
#define BUF_FLOATS (A_FLOATS + B_FLOATS)   // 12672
#define GEMM_SMEM (2 * BUF_FLOATS * 4)     // 101376 bytes

__global__ __launch_bounds__(256, 1)
void tc_gemm_kernel(const float* __restrict__ A, const float* __restrict__ Wt,
                    const float* __restrict__ bias, float* __restrict__ C, int N)
{
    extern __shared__ __align__(16) float smem[];

    const int tid  = threadIdx.x;
    const int wid  = tid >> 5;
    const int lane = tid & 31;
    const int grp  = lane >> 2;        // 0..7
    const int tig  = lane & 3;         // 0..3
    const int wm   = wid & 3;          // warp row (M): 4 warps * 64 rows
    const int wn   = wid >> 2;         // warp col (N): 2 warps * 48 cols
    const int n0   = blockIdx.x * 96;
    const int row0 = blockIdx.y * 256;

    // global-load staging registers
    float4 gA[8], gB[3];

    auto LDG = [&](int t) {
        const int k0 = t * 32;
#pragma unroll
        for (int i = 0; i < 8; ++i) {
            int f = tid + i * 256;             // < 2048 float4 (256 rows x 8)
            int r = f >> 3;
            int c = (f & 7) * 4;
            gA[i] = *(const float4*)&A[(size_t)(row0 + r) * Kdim + k0 + c];
        }
#pragma unroll
        for (int i = 0; i < 3; ++i) {
            int f = tid + i * 256;             // < 768 float4 (96 rows x 8)
            int r = f >> 3;
            int c = (f & 7) * 4;
            gB[i] = *(const float4*)&Wt[(size_t)(n0 + r) * Kdim + k0 + c];
        }
    };
    auto STS = [&](int buf) {
        float* As = smem + buf * BUF_FLOATS;
        float* Bs = As + A_FLOATS;
#pragma unroll
        for (int i = 0; i < 8; ++i) {
            int f = tid + i * 256;
            int r = f >> 3;
            int c = (f & 7) * 4;
            float4 v = gA[i];
            v.x = to_tf32(v.x); v.y = to_tf32(v.y);
            v.z = to_tf32(v.z); v.w = to_tf32(v.w);
            *(float4*)&As[r * LDA_PAD + c] = v;
        }
#pragma unroll
        for (int i = 0; i < 3; ++i) {
            int f = tid + i * 256;
            int r = f >> 3;
            int c = (f & 7) * 4;
            float4 v = gB[i];
            v.x = to_tf32(v.x); v.y = to_tf32(v.y);
            v.z = to_tf32(v.z); v.w = to_tf32(v.w);
            *(float4*)&Bs[r * LDA_PAD + c] = v;
        }
    };

    float4 acc[4][6];
#pragma unroll
    for (int mt = 0; mt < 4; ++mt)
#pragma unroll
        for (int nt = 0; nt < 6; ++nt)
            acc[mt][nt] = make_float4(0.f, 0.f, 0.f, 0.f);

    LDG(0);
    STS(0);
    __syncthreads();

#pragma unroll 1
    for (int t = 0; t < 6; ++t) {              // K = 192 = 6 * 32
        if (t < 5) LDG(t + 1);
        const float* As = smem + (t & 1) * BUF_FLOATS;
        const float* Bs = As + A_FLOATS;
#pragma unroll
        for (int ks = 0; ks < 4; ++ks) {
            const int kk = ks * 8;
            uint32_t af[4][4];
#pragma unroll
            for (int mt = 0; mt < 4; ++mt) {
                const float* ap = As + (wm * 64 + mt * 16 + grp) * LDA_PAD + kk + tig;
                af[mt][0] = __float_as_uint(ap[0]);
                af[mt][1] = __float_as_uint(ap[8 * LDA_PAD]);
                af[mt][2] = __float_as_uint(ap[4]);
                af[mt][3] = __float_as_uint(ap[8 * LDA_PAD + 4]);
            }
#pragma unroll
            for (int nt = 0; nt < 6; ++nt) {
                const float* bp = Bs + (wn * 48 + nt * 8 + grp) * LDA_PAD + kk + tig;
                uint32_t b0 = __float_as_uint(bp[0]);
                uint32_t b1 = __float_as_uint(bp[4]);
#pragma unroll
                for (int mt = 0; mt < 4; ++mt)
                    mma_tf32(acc[mt][nt], af[mt][0], af[mt][1],
                             af[mt][2], af[mt][3], b0, b1);
            }
        }
        if (t < 5) {
            STS((t + 1) & 1);
            __syncthreads();
        }
    }

    // epilogue: bias + store (float2, 32B-contiguous per 4-lane group)
#pragma unroll
    for (int mt = 0; mt < 4; ++mt) {
        int row = row0 + wm * 64 + mt * 16 + grp;
#pragma unroll
        for (int nt = 0; nt < 6; ++nt) {
            int col = n0 + wn * 48 + nt * 8 + tig * 2;
            float2 bv = *(const float2*)&bias[col];
            float4 a = acc[mt][nt];
            float2 v0 = {a.x + bv.x, a.y + bv.y};
            float2 v1 = {a.z + bv.x, a.w + bv.y};
            *(float2*)&C[(size_t)row * N + col]       = v0;
            *(float2*)&C[(size_t)(row + 8) * N + col] = v1;
        }
    }
}

// ---------------- K2: 3x3 depthwise conv, SAME padding, 576 channels -------
__global__ void dwconv_kernel(const float* __restrict__ in,
                              const float* __restrict__ wdw,
                              const float* __restrict__ bias,
                              float* __restrict__ out)
{
    const int NC4 = C3 / 4;  // 144
    int gid = blockIdx.x * 256 + threadIdx.x;
    if (gid >= Bsz * HWn * NC4) return;
    int c4  = gid % NC4;
    int pix = gid / NC4;
    int x = pix & (Ww - 1);
    int y = (pix >> 8) & (Hh - 1);

    const float4* in4 = (const float4*)in;
    const float4* w4  = (const float4*)wdw;
    float4 acc = ((const float4*)bias)[c4];
#pragma unroll
    for (int dy = -1; dy <= 1; ++dy) {
        int yy = y + dy;
        if ((unsigned)yy >= (unsigned)Hh) continue;
#pragma unroll
        for (int dx = -1; dx <= 1; ++dx) {
            int xx = x + dx;
            if ((unsigned)xx >= (unsigned)Ww) continue;
            float4 v  = in4[(size_t)(pix + dy * Ww + dx) * NC4 + c4];
            float4 wv = w4[((dy + 1) * 3 + (dx + 1)) * NC4 + c4];
            acc.x += v.x * wv.x;
            acc.y += v.y * wv.y;
            acc.z += v.z * wv.z;
            acc.w += v.w * wv.w;
        }
    }
    ((float4*)out)[(size_t)pix * NC4 + c4] = acc;
}

// ---------------- K3: per-channel sum of squares over HW (q & k only) -------
// grid (256 hw-splits of 256, 3 channel-chunks of 128, 2 batch)
__global__ void norms_kernel(const float* __restrict__ qkv, float* __restrict__ norms)
{
    int b  = blockIdx.z;
    int cg = blockIdx.y;
    int sp = blockIdx.x;
    int t  = threadIdx.x;
    int ch = t & 127;
    int hs = t >> 7;
    int chg = cg * 128 + ch;     // 0..383

    const float* base = qkv + (size_t)b * HWn * C3 + chg;
    float s = 0.f;
#pragma unroll 8
    for (int i = 0; i < 128; ++i) {
        int hw = sp * 256 + i * 2 + hs;
        float v = base[(size_t)hw * C3];
        s += v * v;
    }
    __shared__ float red[256];
    red[t] = s;
    __syncthreads();
    if (hs == 0)
        atomicAdd(&norms[b * 384 + chg], red[t] + red[t + 128]);
}

// ---------------- K4: raw gram S[bh][i][j] = sum_hw q_i * k_j (split-K) ----
__global__ __launch_bounds__(64)
void gram_kernel(const float* __restrict__ qkv, float* __restrict__ S)
{
    int bh   = blockIdx.x;
    int sp   = blockIdx.y;
    int b    = bh >> 2;
    int head = bh & 3;
    int t    = threadIdx.x;
    int ti   = t & 7;
    int tj   = t >> 3;

    __shared__ float sqk[2 * 16 * 48];
    float acc[6][6];
#pragma unroll
    for (int i = 0; i < 6; ++i)
#pragma unroll
        for (int j = 0; j < 6; ++j) acc[i][j] = 0.f;

    const int chQ = head * CPH;
    const int chK = 192 + head * CPH;
    size_t rowbase = (size_t)(b * HWn + sp * 512) * C3;

#pragma unroll 1
    for (int chunk = 0; chunk < 32; ++chunk) {
        size_t cb = rowbase + (size_t)chunk * 16 * C3;
#pragma unroll
        for (int p = 0; p < 24; ++p) {
            int idx = t + p * 64;
            int which = idx >= 768;
            int r = idx - which * 768;
            int hwl = r / 48;
            int c = r - hwl * 48;
            sqk[which * 768 + hwl * 48 + c] =
                qkv[cb + (size_t)hwl * C3 + (which ? chK : chQ) + c];
        }
        __syncthreads();
#pragma unroll 8
        for (int kk = 0; kk < 16; ++kk) {
            float qa[6], kb[6];
#pragma unroll
            for (int ii = 0; ii < 6; ++ii) qa[ii] = sqk[kk * 48 + ti * 6 + ii];
#pragma unroll
            for (int jj = 0; jj < 6; ++jj) kb[jj] = sqk[768 + kk * 48 + tj * 6 + jj];
#pragma unroll
            for (int ii = 0; ii < 6; ++ii)
#pragma unroll
                for (int jj = 0; jj < 6; ++jj) acc[ii][jj] += qa[ii] * kb[jj];
        }
        __syncthreads();
    }

    float* Sb = S + (size_t)bh * CPH * CPH;
#pragma unroll
    for (int ii = 0; ii < 6; ++ii)
#pragma unroll
        for (int jj = 0; jj < 6; ++jj)
            atomicAdd(&Sb[(ti * 6 + ii) * CPH + tj * 6 + jj], acc[ii][jj]);
}

// ---------------- K5: normalize logits, temperature, softmax ----------------
__global__ void softmax_kernel(const float* __restrict__ S, const float* __restrict__ norms,
                               const float* __restrict__ temp, float* __restrict__ A)
{
    int bh = blockIdx.x;
    int b = bh >> 2, head = bh & 3;
    int t = threadIdx.x;

    __shared__ float kn[CPH];
    if (t < CPH)
        kn[t] = fmaxf(sqrtf(norms[b * 384 + 192 + head * CPH + t]), 1e-12f);
    __syncthreads();

    if (t < CPH) {
        float qn = fmaxf(sqrtf(norms[b * 384 + head * CPH + t]), 1e-12f);
        float tp = temp[head];
        const float* Sr = S + ((size_t)bh * CPH + t) * CPH;
        float l[CPH];
        float m = -1e30f;
#pragma unroll
        for (int j = 0; j < CPH; ++j) {
            l[j] = Sr[j] * tp / (qn * kn[j]);
            m = fmaxf(m, l[j]);
        }
        float s = 0.f;
#pragma unroll
        for (int j = 0; j < CPH; ++j) {
            float e = expf(l[j] - m);
            l[j] = e;
            s += e;
        }
        float inv = 1.f / s;
        float* Ab = A + (size_t)bh * CPH * CPH;
#pragma unroll
        for (int j = 0; j < CPH; ++j)
            Ab[j * CPH + t] = l[j] * inv;   // transposed store
    }
}

// ---------------- K6: out[hw, head*48+i] = sum_j A[i][j] * v[j][hw] --------
__global__ __launch_bounds__(64)
void apply_kernel(const float* __restrict__ qkv, const float* __restrict__ A,
                  float* __restrict__ out)
{
    int hw0  = blockIdx.x * 128;
    int head = blockIdx.y;
    int b    = blockIdx.z;
    int t    = threadIdx.x;

    __shared__ __align__(16) float As2[CPH * CPH];
    __shared__ float Vs[128 * 49];

    const float* Ab = A + (size_t)(b * HEADS + head) * CPH * CPH;
#pragma unroll
    for (int p = 0; p < 36; ++p) As2[t + p * 64] = Ab[t + p * 64];

    size_t base = (size_t)(b * HWn + hw0) * C3 + 384 + head * CPH;
#pragma unroll 4
    for (int p = 0; p < 96; ++p) {
        int idx = t + p * 64;
        int hwl = idx / 48;
        int c   = idx - hwl * 48;
        Vs[hwl * 49 + c] = qkv[base + (size_t)hwl * C3 + c];
    }
    __syncthreads();

    float acc0[CPH], acc1[CPH];
#pragma unroll
    for (int i = 0; i < CPH; ++i) { acc0[i] = 0.f; acc1[i] = 0.f; }

#pragma unroll 2
    for (int j = 0; j < CPH; ++j) {
        float v0 = Vs[t * 49 + j];
        float v1 = Vs[(t + 64) * 49 + j];
#pragma unroll
        for (int i4 = 0; i4 < 12; ++i4) {
            float4 a4 = *(const float4*)&As2[j * CPH + i4 * 4];
            acc0[i4 * 4 + 0] += a4.x * v0;  acc1[i4 * 4 + 0] += a4.x * v1;
            acc0[i4 * 4 + 1] += a4.y * v0;  acc1[i4 * 4 + 1] += a4.y * v1;
            acc0[i4 * 4 + 2] += a4.z * v0;  acc1[i4 * 4 + 2] += a4.z * v1;
            acc0[i4 * 4 + 3] += a4.w * v0;  acc1[i4 * 4 + 3] += a4.w * v1;
        }
    }

    __syncthreads();
#pragma unroll
    for (int i = 0; i < CPH; ++i) {
        Vs[t * 49 + i]        = acc0[i];
        Vs[(t + 64) * 49 + i] = acc1[i];
    }
    __syncthreads();

    size_t obase = (size_t)(b * HWn + hw0) * Cc + head * CPH;
#pragma unroll 4
    for (int p = 0; p < 96; ++p) {
        int idx = t + p * 64;
        int hwl = idx / 48;
        int c   = idx - hwl * 48;
        out[obase + (size_t)hwl * Cc + c] = Vs[hwl * 49 + c];
    }
}

// ---------------- host launcher --------------------------------------------
extern "C" void kernel_launch(void* const* d_in, const int* in_sizes, int n_in,
                              void* d_out, int out_size)
{
    const float* x           = (const float*)d_in[0];
    const float* w_qkv       = (const float*)d_in[1];
    const float* b_qkv       = (const float*)d_in[2];
    const float* w_dw        = (const float*)d_in[3];
    const float* b_dw        = (const float*)d_in[4];
    const float* temperature = (const float*)d_in[5];
    const float* w_out       = (const float*)d_in[6];
    const float* b_out       = (const float*)d_in[7];
    float* out = (float*)d_out;

    float *qkv1, *qkv2, *attn, *norms, *S, *A, *wt1, *wt2;
    cudaGetSymbolAddress((void**)&qkv1,  g_qkv1);
    cudaGetSymbolAddress((void**)&qkv2,  g_qkv2);
    cudaGetSymbolAddress((void**)&attn,  g_attn);
    cudaGetSymbolAddress((void**)&norms, g_norms);
    cudaGetSymbolAddress((void**)&S,     g_S);
    cudaGetSymbolAddress((void**)&A,     g_A);
    cudaGetSymbolAddress((void**)&wt1,   g_wt1);
    cudaGetSymbolAddress((void**)&wt2,   g_wt2);

    cudaFuncSetAttribute(tc_gemm_kernel,
                         cudaFuncAttributeMaxDynamicSharedMemorySize, GEMM_SMEM);

    // K0: zero accumulators (every graph replay)
    zero_kernel<<<72, 256>>>(norms, S);
    // transpose weights into K-major scratch
    transpose_w_kernel<<<(Kdim * C3 + 255) / 256, 256>>>(w_qkv, wt1, C3);
    transpose_w_kernel<<<(Kdim * Cc + 255) / 256, 256>>>(w_out, wt2, Cc);
    // K1: qkv 1x1 conv  [131072,192] x [192,576]  (tf32 mma.sync, BM=256)
    tc_gemm_kernel<<<dim3(C3 / 96, Mrows / 256), 256, GEMM_SMEM>>>(x, wt1, b_qkv, qkv1, C3);
    // K2: 3x3 depthwise conv
    dwconv_kernel<<<(Bsz * HWn * (C3 / 4)) / 256, 256>>>(qkv1, w_dw, b_dw, qkv2);
    // K3: L2-norm sums for q and k
    norms_kernel<<<dim3(256, 3, Bsz), 256>>>(qkv2, norms);
    // K4: gram logits
    gram_kernel<<<dim3(Bsz * HEADS, 128), 64>>>(qkv2, S);
    // K5: normalize + temperature + softmax
    softmax_kernel<<<Bsz * HEADS, 64>>>(S, norms, temperature, A);
    // K6: attn @ v
    apply_kernel<<<dim3(HWn / 128, HEADS, Bsz), 64>>>(qkv2, A, attn);
    // K7: output 1x1 conv [131072,192] x [192,192]  (tf32 mma.sync, BM=256)
    tc_gemm_kernel<<<dim3(Cc / 96, Mrows / 256), 256, GEMM_SMEM>>>(attn, wt2, b_out, out, Cc);
}

// round 15
// speedup vs baseline: 1.6399x; 1.0179x over previous
#include <cuda_runtime.h>
#include <cstdint>
#include <math.h>

// Problem constants (fixed by setup_inputs)
#define Bsz    2
#define Hh     256
#define Ww     256
#define Cc     192
#define C3     576
#define HEADS  4
#define CPH    48
#define HWn    65536
#define Mrows  131072   // B*H*W
#define Kdim   192

// ---------------- scratch (static device globals: allocation-free) ----------
__device__ float g_qkv1[(size_t)Mrows * C3];     // after 1x1 qkv conv
__device__ float g_qkv2[(size_t)Mrows * C3];     // after depthwise conv
__device__ float g_attn[(size_t)Mrows * Cc];     // rounded x, later attention out
__device__ float g_norms[Bsz * 384];             // sumsq q(0..191), k(192..383)
__device__ float g_S[Bsz * HEADS * CPH * CPH];   // raw gram logits
__device__ float g_A[Bsz * HEADS * CPH * CPH];   // softmax, stored [bh][j][i]
__device__ float g_wt1[C3 * Kdim];               // w_qkv^T  [576][192] (tf32-rounded)
__device__ float g_wt2[Cc * Kdim];               // w_out^T  [192][192] (tf32-rounded)

__device__ __forceinline__ float to_tf32(float x) {
    float r;
    asm("cvt.rna.tf32.f32 %0, %1;" : "=f"(r) : "f"(x));
    return r;
}

// ---------------- K0: zero the accumulated buffers (every replay) -----------
__global__ void zero_kernel(float* __restrict__ norms, float* __restrict__ S)
{
    int t = blockIdx.x * 256 + threadIdx.x;
    if (t < Bsz * 384) norms[t] = 0.f;
    if (t < Bsz * HEADS * CPH * CPH) S[t] = 0.f;
}

// ---------------- round x -> tf32 copy (A operand of GEMM1) -----------------
__global__ void round_x_kernel(const float4* __restrict__ in,
                               float4* __restrict__ out, int n4)
{
    int i = blockIdx.x * 256 + threadIdx.x;
    if (i >= n4) return;
    float4 v = in[i];
    v.x = to_tf32(v.x); v.y = to_tf32(v.y);
    v.z = to_tf32(v.z); v.w = to_tf32(v.w);
    out[i] = v;
}

// ---------------- transpose W [192,N] -> Wt [N,192] (tf32-rounded) ----------
__global__ void transpose_w_kernel(const float* __restrict__ w,
                                   float* __restrict__ wt, int N)
{
    int idx = blockIdx.x * 256 + threadIdx.x;
    if (idx >= Kdim * N) return;
    int n = idx / Kdim;
    int k = idx - n * Kdim;
    wt[idx] = to_tf32(w[k * N + n]);
}

// ===================== tf32 mma.sync GEMM: C = A * Wt^T + bias ==============
// BM=128, BN=96, BK=32, 256 threads = 8 warps (4 over M x 2 over N).
// cp.async 3-stage ring; 32-float rows with XOR-chunk swizzle:
//   phys chunk = (logical_chunk ^ (row&7)), 4 floats per chunk.
// Fragment LDS bank = 4*((2ks+c)^grp)+tig -> bijective over 32 banks.
// Inputs A and Wt are PRE-ROUNDED to tf32 (no cvt in this kernel).

__device__ __forceinline__ void mma_tf32(float4& d,
                                         uint32_t a0, uint32_t a1,
                                         uint32_t a2, uint32_t a3,
                                         uint32_t b0, uint32_t b1)
{
    asm volatile(
        "mma.sync.aligned.m16n8k8.row.col.f32.tf32.tf32.f32 "
        "{%0,%1,%2,%3}, {%4,%5,%6,%7}, {%8,%9}, {%0,%1,%2,%3};"
        : "+f"(d.x), "+f"(d.y), "+f"(d.z), "+f"(d.w)
        : "r"(a0), "r"(a1), "r"(a2), "r"(a3), "r"(b0), "r"(b1));
}

#define STAGE_FLOATS 7168                  // (128 + 96) * 32
#define GEMM_SMEM    (3 * STAGE_FLOATS * 4)  // 86016 bytes

__global__ __launch_bounds__(256, 2)
void tc_gemm_kernel(const float* __restrict__ A, const float* __restrict__ Wt,
                    const float* __restrict__ bias, float* __restrict__ C, int N)
{
    extern __shared__ __align__(16) float smem[];

    const int tid  = threadIdx.x;
    const int wid  = tid >> 5;
    const int lane = tid & 31;
    const int grp  = lane >> 2;        // 0..7
    const int tig  = lane & 3;         // 0..3
    const int wm   = wid & 3;          // warp row (M): 4 warps * 32 rows
    const int wn   = wid >> 2;         // warp col (N): 2 warps * 48 cols
    const int n0   = blockIdx.x * 96;
    const int row0 = blockIdx.y * 128;

    auto cp_stage = [&](int t, int slot) {
        const int k0 = t * 32;
        float* sa = smem + slot * STAGE_FLOATS;
        float* sb = sa + 4096;                    // 128*32
#pragma unroll
        for (int i = 0; i < 4; ++i) {
            int q = tid + i * 256;                // < 1024
            int r = q >> 3, cc = q & 7;
            uint32_t dst = (uint32_t)__cvta_generic_to_shared(
                sa + r * 32 + ((cc ^ (r & 7)) << 2));
            const float* src = &A[(size_t)(row0 + r) * Kdim + k0 + cc * 4];
            asm volatile("cp.async.cg.shared.global [%0], [%1], 16;"
                         :: "r"(dst), "l"(src) : "memory");
        }
#pragma unroll
        for (int i = 0; i < 3; ++i) {
            int q = tid + i * 256;                // < 768
            int r = q >> 3, cc = q & 7;
            uint32_t dst = (uint32_t)__cvta_generic_to_shared(
                sb + r * 32 + ((cc ^ (r & 7)) << 2));
            const float* src = &Wt[(size_t)(n0 + r) * Kdim + k0 + cc * 4];
            asm volatile("cp.async.cg.shared.global [%0], [%1], 16;"
                         :: "r"(dst), "l"(src) : "memory");
        }
        asm volatile("cp.async.commit_group;" ::: "memory");
    };

    float4 acc[2][6];
#pragma unroll
    for (int mt = 0; mt < 2; ++mt)
#pragma unroll
        for (int nt = 0; nt < 6; ++nt)
            acc[mt][nt] = make_float4(0.f, 0.f, 0.f, 0.f);

    cp_stage(0, 0);
    cp_stage(1, 1);

#pragma unroll 1
    for (int t = 0; t < 6; ++t) {              // K = 192 = 6 * 32
        if (t < 5) asm volatile("cp.async.wait_group 1;" ::: "memory");
        else       asm volatile("cp.async.wait_group 0;" ::: "memory");
        __syncthreads();
        if (t + 2 < 6) cp_stage(t + 2, (t + 2) % 3);

        const float* As = smem + (t % 3) * STAGE_FLOATS;
        const float* Bs = As + 4096;
#pragma unroll
        for (int ks = 0; ks < 4; ++ks) {
            const int p0 = (((2 * ks)     ^ grp) << 2) + tig;
            const int p1 = (((2 * ks + 1) ^ grp) << 2) + tig;
            uint32_t af[2][4];
#pragma unroll
            for (int mt = 0; mt < 2; ++mt) {
                const float* ap = As + (wm * 32 + mt * 16 + grp) * 32;
                af[mt][0] = __float_as_uint(ap[p0]);
                af[mt][1] = __float_as_uint(ap[256 + p0]);   // +8 rows
                af[mt][2] = __float_as_uint(ap[p1]);
                af[mt][3] = __float_as_uint(ap[256 + p1]);
            }
#pragma unroll
            for (int nt = 0; nt < 6; ++nt) {
                const float* bp = Bs + (wn * 48 + nt * 8 + grp) * 32;
                uint32_t b0 = __float_as_uint(bp[p0]);
                uint32_t b1 = __float_as_uint(bp[p1]);
                mma_tf32(acc[0][nt], af[0][0], af[0][1], af[0][2], af[0][3], b0, b1);
                mma_tf32(acc[1][nt], af[1][0], af[1][1], af[1][2], af[1][3], b0, b1);
            }
        }
    }

    // epilogue: bias + store (float2, 32B-contiguous per 4-lane group)
#pragma unroll
    for (int mt = 0; mt < 2; ++mt) {
        int row = row0 + wm * 32 + mt * 16 + grp;
#pragma unroll
        for (int nt = 0; nt < 6; ++nt) {
            int col = n0 + wn * 48 + nt * 8 + tig * 2;
            float2 bv = *(const float2*)&bias[col];
            float4 a = acc[mt][nt];
            float2 v0 = {a.x + bv.x, a.y + bv.y};
            float2 v1 = {a.z + bv.x, a.w + bv.y};
            *(float2*)&C[(size_t)row * N + col]       = v0;
            *(float2*)&C[(size_t)(row + 8) * N + col] = v1;
        }
    }
}

// ---------------- K2: 3x3 depthwise conv, SAME padding, 576 channels -------
__global__ void dwconv_kernel(const float* __restrict__ in,
                              const float* __restrict__ wdw,
                              const float* __restrict__ bias,
                              float* __restrict__ out)
{
    const int NC4 = C3 / 4;  // 144
    int gid = blockIdx.x * 256 + threadIdx.x;
    if (gid >= Bsz * HWn * NC4) return;
    int c4  = gid % NC4;
    int pix = gid / NC4;
    int x = pix & (Ww - 1);
    int y = (pix >> 8) & (Hh - 1);

    const float4* in4 = (const float4*)in;
    const float4* w4  = (const float4*)wdw;
    float4 acc = ((const float4*)bias)[c4];
#pragma unroll
    for (int dy = -1; dy <= 1; ++dy) {
        int yy = y + dy;
        if ((unsigned)yy >= (unsigned)Hh) continue;
#pragma unroll
        for (int dx = -1; dx <= 1; ++dx) {
            int xx = x + dx;
            if ((unsigned)xx >= (unsigned)Ww) continue;
            float4 v  = in4[(size_t)(pix + dy * Ww + dx) * NC4 + c4];
            float4 wv = w4[((dy + 1) * 3 + (dx + 1)) * NC4 + c4];
            acc.x += v.x * wv.x;
            acc.y += v.y * wv.y;
            acc.z += v.z * wv.z;
            acc.w += v.w * wv.w;
        }
    }
    ((float4*)out)[(size_t)pix * NC4 + c4] = acc;
}

// ---------------- K3: per-channel sum of squares over HW (q & k only) -------
// grid (256 hw-splits of 256, 3 channel-chunks of 128, 2 batch)
__global__ void norms_kernel(const float* __restrict__ qkv, float* __restrict__ norms)
{
    int b  = blockIdx.z;
    int cg = blockIdx.y;
    int sp = blockIdx.x;
    int t  = threadIdx.x;
    int ch = t & 127;
    int hs = t >> 7;
    int chg = cg * 128 + ch;     // 0..383

    const float* base = qkv + (size_t)b * HWn * C3 + chg;
    float s = 0.f;
#pragma unroll 8
    for (int i = 0; i < 128; ++i) {
        int hw = sp * 256 + i * 2 + hs;
        float v = base[(size_t)hw * C3];
        s += v * v;
    }
    __shared__ float red[256];
    red[t] = s;
    __syncthreads();
    if (hs == 0)
        atomicAdd(&norms[b * 384 + chg], red[t] + red[t + 128]);
}

// ---------------- K4: raw gram S[bh][i][j] = sum_hw q_i * k_j (split-K) ----
__global__ __launch_bounds__(64)
void gram_kernel(const float* __restrict__ qkv, float* __restrict__ S)
{
    int bh   = blockIdx.x;
    int sp   = blockIdx.y;
    int b    = bh >> 2;
    int head = bh & 3;
    int t    = threadIdx.x;
    int ti   = t & 7;
    int tj   = t >> 3;

    __shared__ float sqk[2 * 16 * 48];
    float acc[6][6];
#pragma unroll
    for (int i = 0; i < 6; ++i)
#pragma unroll
        for (int j = 0; j < 6; ++j) acc[i][j] = 0.f;

    const int chQ = head * CPH;
    const int chK = 192 + head * CPH;
    size_t rowbase = (size_t)(b * HWn + sp * 512) * C3;

    const int hwl0 = (t >= 48);
    const int c0   = t - 48 * hwl0;

#pragma unroll 1
    for (int chunk = 0; chunk < 32; ++chunk) {
        size_t cb = rowbase + (size_t)chunk * 16 * C3;
        {
            int hwl = hwl0, c = c0;
#pragma unroll
            for (int p = 0; p < 24; ++p) {
                if (p == 12) { hwl = hwl0; c = c0; }
                int which = (p >= 12);
                sqk[which * 768 + hwl * 48 + c] =
                    qkv[cb + (size_t)hwl * C3 + (which ? chK : chQ) + c];
                c += 16; hwl += 1;
                if (c >= 48) { c -= 48; hwl += 1; }
            }
        }
        __syncthreads();
#pragma unroll 8
        for (int kk = 0; kk < 16; ++kk) {
            float qa[6], kb[6];
#pragma unroll
            for (int ii = 0; ii < 6; ++ii) qa[ii] = sqk[kk * 48 + ti * 6 + ii];
#pragma unroll
            for (int jj = 0; jj < 6; ++jj) kb[jj] = sqk[768 + kk * 48 + tj * 6 + jj];
#pragma unroll
            for (int ii = 0; ii < 6; ++ii)
#pragma unroll
                for (int jj = 0; jj < 6; ++jj) acc[ii][jj] += qa[ii] * kb[jj];
        }
        __syncthreads();
    }

    float* Sb = S + (size_t)bh * CPH * CPH;
#pragma unroll
    for (int ii = 0; ii < 6; ++ii)
#pragma unroll
        for (int jj = 0; jj < 6; ++jj)
            atomicAdd(&Sb[(ti * 6 + ii) * CPH + tj * 6 + jj], acc[ii][jj]);
}

// ---------------- K5: normalize logits, temperature, softmax ----------------
__global__ void softmax_kernel(const float* __restrict__ S, const float* __restrict__ norms,
                               const float* __restrict__ temp, float* __restrict__ A)
{
    int bh = blockIdx.x;
    int b = bh >> 2, head = bh & 3;
    int t = threadIdx.x;

    __shared__ float kn[CPH];
    if (t < CPH)
        kn[t] = fmaxf(sqrtf(norms[b * 384 + 192 + head * CPH + t]), 1e-12f);
    __syncthreads();

    if (t < CPH) {
        float qn = fmaxf(sqrtf(norms[b * 384 + head * CPH + t]), 1e-12f);
        float tp = temp[head];
        const float* Sr = S + ((size_t)bh * CPH + t) * CPH;
        float l[CPH];
        float m = -1e30f;
#pragma unroll
        for (int j = 0; j < CPH; ++j) {
            l[j] = Sr[j] * tp / (qn * kn[j]);
            m = fmaxf(m, l[j]);
        }
        float s = 0.f;
#pragma unroll
        for (int j = 0; j < CPH; ++j) {
            float e = expf(l[j] - m);
            l[j] = e;
            s += e;
        }
        float inv = 1.f / s;
        float* Ab = A + (size_t)bh * CPH * CPH;
#pragma unroll
        for (int j = 0; j < CPH; ++j)
            Ab[j * CPH + t] = l[j] * inv;   // transposed store
    }
}

// ---------------- K6: out[hw, head*48+i] = sum_j A[i][j] * v[j][hw] --------
// Output rounded to tf32 (it is the A operand of GEMM2).
__global__ __launch_bounds__(64)
void apply_kernel(const float* __restrict__ qkv, const float* __restrict__ A,
                  float* __restrict__ out)
{
    int hw0  = blockIdx.x * 128;
    int head = blockIdx.y;
    int b    = blockIdx.z;
    int t    = threadIdx.x;

    __shared__ __align__(16) float As2[CPH * CPH];
    __shared__ float Vs[128 * 49];

    const float* Ab = A + (size_t)(b * HEADS + head) * CPH * CPH;
#pragma unroll
    for (int p = 0; p < 36; ++p) As2[t + p * 64] = Ab[t + p * 64];

    const int hwl0 = (t >= 48);
    const int c0   = t - 48 * hwl0;

    size_t base = (size_t)(b * HWn + hw0) * C3 + 384 + head * CPH;
    {
        int hwl = hwl0, c = c0;
#pragma unroll 4
        for (int p = 0; p < 96; ++p) {
            Vs[hwl * 49 + c] = qkv[base + (size_t)hwl * C3 + c];
            c += 16; hwl += 1;
            if (c >= 48) { c -= 48; hwl += 1; }
        }
    }
    __syncthreads();

    float acc0[CPH], acc1[CPH];
#pragma unroll
    for (int i = 0; i < CPH; ++i) { acc0[i] = 0.f; acc1[i] = 0.f; }

#pragma unroll 2
    for (int j = 0; j < CPH; ++j) {
        float v0 = Vs[t * 49 + j];
        float v1 = Vs[(t + 64) * 49 + j];
#pragma unroll
        for (int i4 = 0; i4 < 12; ++i4) {
            float4 a4 = *(const float4*)&As2[j * CPH + i4 * 4];
            acc0[i4 * 4 + 0] += a4.x * v0;  acc1[i4 * 4 + 0] += a4.x * v1;
            acc0[i4 * 4 + 1] += a4.y * v0;  acc1[i4 * 4 + 1] += a4.y * v1;
            acc0[i4 * 4 + 2] += a4.z * v0;  acc1[i4 * 4 + 2] += a4.z * v1;
            acc0[i4 * 4 + 3] += a4.w * v0;  acc1[i4 * 4 + 3] += a4.w * v1;
        }
    }

    __syncthreads();
#pragma unroll
    for (int i = 0; i < CPH; ++i) {
        Vs[t * 49 + i]        = to_tf32(acc0[i]);
        Vs[(t + 64) * 49 + i] = to_tf32(acc1[i]);
    }
    __syncthreads();

    size_t obase = (size_t)(b * HWn + hw0) * Cc + head * CPH;
    {
        int hwl = hwl0, c = c0;
#pragma unroll 4
        for (int p = 0; p < 96; ++p) {
            out[obase + (size_t)hwl * Cc + c] = Vs[hwl * 49 + c];
            c += 16; hwl += 1;
            if (c >= 48) { c -= 48; hwl += 1; }
        }
    }
}

// ---------------- host launcher --------------------------------------------
extern "C" void kernel_launch(void* const* d_in, const int* in_sizes, int n_in,
                              void* d_out, int out_size)
{
    const float* x           = (const float*)d_in[0];
    const float* w_qkv       = (const float*)d_in[1];
    const float* b_qkv       = (const float*)d_in[2];
    const float* w_dw        = (const float*)d_in[3];
    const float* b_dw        = (const float*)d_in[4];
    const float* temperature = (const float*)d_in[5];
    const float* w_out       = (const float*)d_in[6];
    const float* b_out       = (const float*)d_in[7];
    float* out = (float*)d_out;

    float *qkv1, *qkv2, *attn, *norms, *S, *A, *wt1, *wt2;
    cudaGetSymbolAddress((void**)&qkv1,  g_qkv1);
    cudaGetSymbolAddress((void**)&qkv2,  g_qkv2);
    cudaGetSymbolAddress((void**)&attn,  g_attn);
    cudaGetSymbolAddress((void**)&norms, g_norms);
    cudaGetSymbolAddress((void**)&S,     g_S);
    cudaGetSymbolAddress((void**)&A,     g_A);
    cudaGetSymbolAddress((void**)&wt1,   g_wt1);
    cudaGetSymbolAddress((void**)&wt2,   g_wt2);

    cudaFuncSetAttribute(tc_gemm_kernel,
                         cudaFuncAttributeMaxDynamicSharedMemorySize, GEMM_SMEM);

    // K0: zero accumulators (every graph replay)
    zero_kernel<<<72, 256>>>(norms, S);
    // round x into g_attn (free buffer until apply_kernel overwrites it)
    round_x_kernel<<<(Mrows * Kdim / 4 + 255) / 256, 256>>>(
        (const float4*)x, (float4*)attn, Mrows * Kdim / 4);
    // transpose + round weights into K-major scratch
    transpose_w_kernel<<<(Kdim * C3 + 255) / 256, 256>>>(w_qkv, wt1, C3);
    transpose_w_kernel<<<(Kdim * Cc + 255) / 256, 256>>>(w_out, wt2, Cc);
    // K1: qkv 1x1 conv  [131072,192] x [192,576]  (tf32 mma.sync + cp.async)
    tc_gemm_kernel<<<dim3(C3 / 96, Mrows / 128), 256, GEMM_SMEM>>>(attn, wt1, b_qkv, qkv1, C3);
    // K2: 3x3 depthwise conv
    dwconv_kernel<<<(Bsz * HWn * (C3 / 4)) / 256, 256>>>(qkv1, w_dw, b_dw, qkv2);
    // K3: L2-norm sums for q and k
    norms_kernel<<<dim3(256, 3, Bsz), 256>>>(qkv2, norms);
    // K4: gram logits
    gram_kernel<<<dim3(Bsz * HEADS, 128), 64>>>(qkv2, S);
    // K5: normalize + temperature + softmax
    softmax_kernel<<<Bsz * HEADS, 64>>>(S, norms, temperature, A);
    // K6: attn @ v  (writes tf32-rounded attn over g_attn)
    apply_kernel<<<dim3(HWn / 128, HEADS, Bsz), 64>>>(qkv2, A, attn);
    // K7: output 1x1 conv [131072,192] x [192,192]  (tf32 mma.sync + cp.async)
    tc_gemm_kernel<<<dim3(Cc / 96, Mrows / 128), 256, GEMM_SMEM>>>(attn, wt2, b_out, out, Cc);
}